// round 1
// baseline (speedup 1.0000x reference)
#include <cuda_runtime.h>
#include <cuda_bf16.h>

// ---------------------------------------------------------------------------
// SpMiddleFHDLite: scatter voxels -> 4x (conv3d + BN + ReLU + mask) dense blocks
// Grid: D=41, H=512, W=512, B=2.
// b1: 3->16  k3 s2 p(1,1,1)  -> (21,256,256)
// b2: 16->32 k3 s2 p(1,1,1)  -> (11,128,128)
// b3: 32->64 k3 s2 p(0,1,1)  -> (5,64,64)
// b4: 64->64 k(3,1,1) s(2,1,1) p0 -> (2,64,64); reshape == same memory layout
// ---------------------------------------------------------------------------

#define EPS 1e-3f

static constexpr int B_  = 2;
static constexpr int D0  = 41, H0 = 512, W0 = 512;
static constexpr long long PLANE0 = (long long)D0 * H0 * W0;           // 10,747,904

// scratch (allocation-free: __device__ globals)
__device__ __align__(256) float         g_dense0[B_ * 3 * D0 * H0 * W0];   // 258 MB
__device__ __align__(256) unsigned char g_mask0 [B_ * D0 * H0 * W0];       // 21.5 MB
__device__ __align__(256) float         g_h1[B_ * 16 * 21 * 256 * 256];    // 176 MB
__device__ __align__(256) unsigned char g_m1[B_ * 21 * 256 * 256];
__device__ __align__(256) float         g_h2[B_ * 32 * 11 * 128 * 128];    // 46 MB
__device__ __align__(256) unsigned char g_m2[B_ * 11 * 128 * 128];
__device__ __align__(256) float         g_h3[B_ * 64 * 5 * 64 * 64];       // 10.5 MB
__device__ __align__(256) unsigned char g_m3[B_ * 5 * 64 * 64];

// ---------------------------------------------------------------------------
__global__ void zero_f4(float4* p, int n4) {
    int i = blockIdx.x * blockDim.x + threadIdx.x;
    if (i < n4) p[i] = make_float4(0.f, 0.f, 0.f, 0.f);
}
__global__ void zero_u4(uint4* p, int n16) {
    int i = blockIdx.x * blockDim.x + threadIdx.x;
    if (i < n16) p[i] = make_uint4(0u, 0u, 0u, 0u);
}

__global__ void scatter_kernel(const float* __restrict__ vf,
                               const int* __restrict__ coors,
                               float* __restrict__ dense,
                               unsigned char* __restrict__ mask, int nv) {
    int i = blockIdx.x * blockDim.x + threadIdx.x;
    if (i >= nv) return;
    int b = coors[4 * i + 0];
    int z = coors[4 * i + 1];
    int y = coors[4 * i + 2];
    int x = coors[4 * i + 3];
    long long sp = (((long long)b * D0 + z) * H0 + y) * W0 + x;
    mask[sp] = 1;
    long long base = (long long)(b * 3) * PLANE0 + ((long long)z * H0 + y) * W0 + x;
    atomicAdd(&dense[base + 0 * PLANE0], vf[3 * i + 0]);
    atomicAdd(&dense[base + 1 * PLANE0], vf[3 * i + 1]);
    atomicAdd(&dense[base + 2 * PLANE0], vf[3 * i + 2]);
}

// ---------------------------------------------------------------------------
// Direct conv + BN + ReLU + mask. Each thread: T=2 ow positions x COG channels.
// blockDim = (32, 8). grid = (OW/64, OH/8, N*OD*(CO/COG)).
// Weights staged in smem as [k][ci][co] (uniform-address broadcast reads).
// ---------------------------------------------------------------------------
template<int CI, int CO, int COG,
         int ID, int IH, int IW, int OD, int OH, int OW,
         int KD, int KH, int KW, int SD, int SH, int SW,
         int PD, int PH, int PW>
__global__ void __launch_bounds__(256)
conv_bn_relu(const float* __restrict__ in, const unsigned char* __restrict__ mi,
             float* __restrict__ out, unsigned char* __restrict__ mo,
             const float* __restrict__ Wt, const float* __restrict__ Ga,
             const float* __restrict__ Be, const float* __restrict__ Rm,
             const float* __restrict__ Rv) {
    constexpr int NCOG = CO / COG;
    constexpr int T = 2;
    constexpr int WSZ = KD * KH * KW * CI * COG;
    extern __shared__ float sw[];

    const int tid = threadIdx.y * 32 + threadIdx.x;
    int zi = blockIdx.z;
    const int cg = zi % NCOG; zi /= NCOG;
    const int od = zi % OD;
    const int n  = zi / OD;

    // stage weights: sw[((kd*KH+kh)*KW+kw)*CI+ci)*COG + co]
    for (int i = tid; i < WSZ; i += 256) {
        int co = i % COG;
        int r  = i / COG;
        int ci = r % CI;
        int k  = r / CI;
        int kw = k % KW;
        int kh = (k / KW) % KH;
        int kd = k / (KW * KH);
        sw[i] = Wt[((((cg * COG + co) * CI + ci) * KD + kd) * KH + kh) * KW + kw];
    }
    __syncthreads();

    const int owb = blockIdx.x * (32 * T) + threadIdx.x;   // t-th output: owb + 32*t
    const int oh  = blockIdx.y * 8 + threadIdx.y;
    if (owb >= OW || oh >= OH) return;

    const int id0 = od * SD - PD;
    const int ih0 = oh * SH - PH;
    const int iwb = owb * SW - PW;

    // mask pass: OR of input-mask over window (== "ones-conv > 0")
    bool any[T];
#pragma unroll
    for (int t = 0; t < T; t++) any[t] = false;
#pragma unroll
    for (int kd = 0; kd < KD; kd++) {
        int id = id0 + kd;
        if (id < 0 || id >= ID) continue;
#pragma unroll
        for (int kh = 0; kh < KH; kh++) {
            int ih = ih0 + kh;
            if (ih < 0 || ih >= IH) continue;
            const unsigned char* mrow = mi + ((long long)(n * ID + id) * IH + ih) * IW;
#pragma unroll
            for (int kw = 0; kw < KW; kw++) {
#pragma unroll
                for (int t = 0; t < T; t++) {
                    int iw = iwb + t * 32 * SW + kw;
                    if (iw >= 0 && iw < IW) any[t] |= (mrow[iw] != 0);
                }
            }
        }
    }
    bool anyany = false;
#pragma unroll
    for (int t = 0; t < T; t++) anyany |= any[t];

    const long long ospat = (long long)OD * OH * OW;
    long long ob[T];
#pragma unroll
    for (int t = 0; t < T; t++)
        ob[t] = (((long long)n * CO + cg * COG) * OD + od) * ((long long)OH * OW)
                + (long long)oh * OW + owb + t * 32;

    if (!anyany) {
#pragma unroll
        for (int co = 0; co < COG; co++)
#pragma unroll
            for (int t = 0; t < T; t++) out[ob[t] + (long long)co * ospat] = 0.f;
        if (cg == 0) {
#pragma unroll
            for (int t = 0; t < T; t++)
                mo[((long long)(n * OD + od) * OH + oh) * OW + owb + t * 32] = 0;
        }
        return;
    }

    float acc[COG][T];
#pragma unroll
    for (int co = 0; co < COG; co++)
#pragma unroll
        for (int t = 0; t < T; t++) acc[co][t] = 0.f;

#pragma unroll
    for (int kd = 0; kd < KD; kd++) {
        int id = id0 + kd;
        if (id < 0 || id >= ID) continue;
        for (int ci = 0; ci < CI; ci++) {
            const float* ib = in + ((long long)(n * CI + ci) * ID + id) * ((long long)IH * IW);
#pragma unroll
            for (int kh = 0; kh < KH; kh++) {
                int ih = ih0 + kh;
                if (ih < 0 || ih >= IH) continue;
                const float* irow = ib + (long long)ih * IW;
#pragma unroll
                for (int kw = 0; kw < KW; kw++) {
                    float v[T];
#pragma unroll
                    for (int t = 0; t < T; t++) {
                        int iw = iwb + t * 32 * SW + kw;
                        v[t] = (iw >= 0 && iw < IW) ? __ldg(irow + iw) : 0.f;
                    }
                    const float* wp = &sw[(((kd * KH + kh) * KW + kw) * CI + ci) * COG];
#pragma unroll
                    for (int co = 0; co < COG; co++) {
                        float wv = wp[co];
#pragma unroll
                        for (int t = 0; t < T; t++)
                            acc[co][t] = fmaf(v[t], wv, acc[co][t]);
                    }
                }
            }
        }
    }

#pragma unroll
    for (int co = 0; co < COG; co++) {
        int cog = cg * COG + co;
        float inv = Ga[cog] * rsqrtf(Rv[cog] + EPS);
        float sh  = fmaf(-Rm[cog], inv, Be[cog]);
#pragma unroll
        for (int t = 0; t < T; t++) {
            float val = any[t] ? fmaxf(fmaf(acc[co][t], inv, sh), 0.f) : 0.f;
            out[ob[t] + (long long)co * ospat] = val;
        }
    }
    if (cg == 0) {
#pragma unroll
        for (int t = 0; t < T; t++)
            mo[((long long)(n * OD + od) * OH + oh) * OW + owb + t * 32] = any[t] ? 1 : 0;
    }
}

// ---------------------------------------------------------------------------
extern "C" void kernel_launch(void* const* d_in, const int* in_sizes, int n_in,
                              void* d_out, int out_size) {
    const float* vf     = (const float*)d_in[0];
    const int*   coors  = (const int*)d_in[1];
    // d_in[2] = batch_size (fixed = 2)
    const float *w1 = (const float*)d_in[3],  *gg1 = (const float*)d_in[4],
                *b1 = (const float*)d_in[5],  *rm1 = (const float*)d_in[6],
                *rv1 = (const float*)d_in[7];
    const float *w2 = (const float*)d_in[8],  *gg2 = (const float*)d_in[9],
                *b2 = (const float*)d_in[10], *rm2 = (const float*)d_in[11],
                *rv2 = (const float*)d_in[12];
    const float *w3 = (const float*)d_in[13], *gg3 = (const float*)d_in[14],
                *b3 = (const float*)d_in[15], *rm3 = (const float*)d_in[16],
                *rv3 = (const float*)d_in[17];
    const float *w4 = (const float*)d_in[18], *gg4 = (const float*)d_in[19],
                *b4 = (const float*)d_in[20], *rm4 = (const float*)d_in[21],
                *rv4 = (const float*)d_in[22];
    float* out = (float*)d_out;

    const int nv = in_sizes[0] / 3;

    float *dense0, *h1, *h2, *h3;
    unsigned char *m0, *m1, *m2, *m3;
    cudaGetSymbolAddress((void**)&dense0, g_dense0);
    cudaGetSymbolAddress((void**)&m0, g_mask0);
    cudaGetSymbolAddress((void**)&h1, g_h1);
    cudaGetSymbolAddress((void**)&m1, g_m1);
    cudaGetSymbolAddress((void**)&h2, g_h2);
    cudaGetSymbolAddress((void**)&m2, g_m2);
    cudaGetSymbolAddress((void**)&h3, g_h3);
    cudaGetSymbolAddress((void**)&m3, g_m3);

    // zero dense grid + mask
    {
        int n4 = (B_ * 3 * D0 * H0 * W0) / 4;
        zero_f4<<<(n4 + 255) / 256, 256>>>((float4*)dense0, n4);
        int n16 = (B_ * D0 * H0 * W0) / 16;
        zero_u4<<<(n16 + 255) / 256, 256>>>((uint4*)m0, n16);
    }
    // scatter voxels
    scatter_kernel<<<(nv + 255) / 256, 256>>>(vf, coors, dense0, m0, nv);

    dim3 blk(32, 8, 1);

    // block1: 3->16, (41,512,512)->(21,256,256)
    {
        auto k = conv_bn_relu<3, 16, 16, 41, 512, 512, 21, 256, 256,
                              3, 3, 3, 2, 2, 2, 1, 1, 1>;
        dim3 grid(256 / 64, 256 / 8, B_ * 21 * 1);
        k<<<grid, blk, 3 * 3 * 3 * 3 * 16 * 4>>>(dense0, m0, h1, m1, w1, gg1, b1, rm1, rv1);
    }
    // block2: 16->32, (21,256,256)->(11,128,128)
    {
        auto k = conv_bn_relu<16, 32, 32, 21, 256, 256, 11, 128, 128,
                              3, 3, 3, 2, 2, 2, 1, 1, 1>;
        size_t smem = 3 * 3 * 3 * 16 * 32 * sizeof(float); // 55296
        cudaFuncSetAttribute((const void*)k, cudaFuncAttributeMaxDynamicSharedMemorySize,
                             (int)smem);
        dim3 grid(128 / 64, 128 / 8, B_ * 11 * 1);
        k<<<grid, blk, smem>>>(h1, m1, h2, m2, w2, gg2, b2, rm2, rv2);
    }
    // block3: 32->64, (11,128,128)->(5,64,64), pad (0,1,1)
    {
        auto k = conv_bn_relu<32, 64, 32, 11, 128, 128, 5, 64, 64,
                              3, 3, 3, 2, 2, 2, 0, 1, 1>;
        size_t smem = 3 * 3 * 3 * 32 * 32 * sizeof(float); // 110592
        cudaFuncSetAttribute((const void*)k, cudaFuncAttributeMaxDynamicSharedMemorySize,
                             (int)smem);
        dim3 grid(64 / 64, 64 / 8, B_ * 5 * 2);
        k<<<grid, blk, smem>>>(h2, m2, h3, m3, w3, gg3, b3, rm3, rv3);
    }
    // block4: 64->64, k(3,1,1) s(2,1,1), (5,64,64)->(2,64,64); writes d_out
    {
        auto k = conv_bn_relu<64, 64, 16, 5, 64, 64, 2, 64, 64,
                              3, 1, 1, 2, 1, 1, 0, 0, 0>;
        size_t smem = 3 * 1 * 1 * 64 * 16 * sizeof(float); // 12288
        dim3 grid(64 / 64, 64 / 8, B_ * 2 * 4);
        k<<<grid, blk, smem>>>(h3, m3, out, m3 /*unused writes ok? no: cg!=0 only*/,
                               w4, gg4, b4, rm4, rv4);
    }
}

// round 2
// speedup vs baseline: 1.4887x; 1.4887x over previous
#include <cuda_runtime.h>
#include <cuda_bf16.h>

// ---------------------------------------------------------------------------
// SpMiddleFHDLite — sparse block1 (scatter-conv + BN pass) + padded dense
// conv blocks 2..4 using packed fma.rn.f32x2.
// b1: 3->16  k3 s2 p(1,1,1) : (41,512,512)->(21,256,256)   [SPARSE]
// b2: 16->32 k3 s2 p(1,1,1) : (21,256,256)->(11,128,128)
// b3: 32->64 k3 s2 p(0,1,1) : (11,128,128)->(5,64,64)
// b4: 64->64 k(3,1,1) s(2,1,1) p0 : (5,64,64)->(2,64,64) == d_out
// ---------------------------------------------------------------------------

#define EPS 1e-3f
typedef unsigned long long u64;

static constexpr int B_ = 2;

// h1 padded for block2's pad (1,1,1): (23,258,258)
static constexpr int PD1 = 23, PH1 = 258, PW1 = 258;
static constexpr long long PLANE1 = (long long)PD1 * PH1 * PW1;   // 1,530,972
// h2 padded for block3's pad (0,1,1): (11,130,130)
static constexpr int PD2 = 11, PH2 = 130, PW2 = 130;
static constexpr long long PLANE2 = (long long)PD2 * PH2 * PW2;   // 185,900

__device__ __align__(256) float         g_h1[B_ * 16 * PLANE1];   // ~196 MB
__device__ __align__(256) unsigned char g_m1[B_ * PLANE1 + 8];    // padded for uint4 zero
__device__ __align__(256) float         g_h2[B_ * 32 * PLANE2];   // ~47.6 MB
__device__ __align__(256) unsigned char g_m2[B_ * PLANE2 + 8];
__device__ __align__(256) float         g_h3[B_ * 64 * 5 * 64 * 64];
__device__ __align__(256) unsigned char g_m3[B_ * 5 * 64 * 64];

// ---------------------------------------------------------------------------
__device__ __forceinline__ u64 pk2(float lo, float hi) {
    u64 r;
    unsigned l = __float_as_uint(lo), h = __float_as_uint(hi);
    asm("mov.b64 %0, {%1,%2};" : "=l"(r) : "r"(l), "r"(h));
    return r;
}
__device__ __forceinline__ void upk2(u64 v, float& lo, float& hi) {
    unsigned l, h;
    asm("mov.b64 {%0,%1}, %2;" : "=r"(l), "=r"(h) : "l"(v));
    lo = __uint_as_float(l); hi = __uint_as_float(h);
}
__device__ __forceinline__ void fma2(u64& d, u64 a, u64 b) {
    asm("fma.rn.f32x2 %0, %1, %2, %0;" : "+l"(d) : "l"(a), "l"(b));
}

// ---------------------------------------------------------------------------
__global__ void zero_f4(float4* p, int n4) {
    int i = blockIdx.x * blockDim.x + threadIdx.x;
    if (i < n4) p[i] = make_float4(0.f, 0.f, 0.f, 0.f);
}
__global__ void zero_u4(uint4* p, int n16) {
    int i = blockIdx.x * blockDim.x + threadIdx.x;
    if (i < n16) p[i] = make_uint4(0u, 0u, 0u, 0u);
}

// ---------------------------------------------------------------------------
// Sparse block1: each thread = (voxel, co). Scatter w.f into h1 accumulator.
// ---------------------------------------------------------------------------
__global__ void __launch_bounds__(256)
scatter_conv1(const float* __restrict__ vf, const int* __restrict__ coors,
              float* __restrict__ h1, unsigned char* __restrict__ m1,
              const float* __restrict__ W, int nv) {
    __shared__ float sw[16 * 3 * 27];
    int tid = threadIdx.x;
    for (int i = tid; i < 16 * 3 * 27; i += 256) sw[i] = W[i]; // [co][ci][k]
    __syncthreads();

    int g = blockIdx.x * 256 + tid;
    int vi = g >> 4, co = g & 15;
    if (vi >= nv) return;

    float f0 = vf[3 * vi], f1 = vf[3 * vi + 1], f2 = vf[3 * vi + 2];
    int b = coors[4 * vi], z = coors[4 * vi + 1], y = coors[4 * vi + 2], x = coors[4 * vi + 3];

    int odl[2], kdl[2], nz = 1;
    if (z & 1) { odl[0] = (z - 1) >> 1; kdl[0] = 2; odl[1] = (z + 1) >> 1; kdl[1] = 0;
                 nz = (((z + 1) >> 1) < 21) ? 2 : 1; }
    else       { odl[0] = z >> 1; kdl[0] = 1; }
    int ohl[2], khl[2], ny = 1;
    if (y & 1) { ohl[0] = (y - 1) >> 1; khl[0] = 2; ohl[1] = (y + 1) >> 1; khl[1] = 0;
                 ny = (((y + 1) >> 1) < 256) ? 2 : 1; }
    else       { ohl[0] = y >> 1; khl[0] = 1; }
    int owl[2], kwl[2], nx = 1;
    if (x & 1) { owl[0] = (x - 1) >> 1; kwl[0] = 2; owl[1] = (x + 1) >> 1; kwl[1] = 0;
                 nx = (((x + 1) >> 1) < 256) ? 2 : 1; }
    else       { owl[0] = x >> 1; kwl[0] = 1; }

    const float* wc = &sw[co * 81];
    float* hc = h1 + (size_t)(b * 16 + co) * PLANE1;
    unsigned char* mb = m1 + (size_t)b * PLANE1;

    for (int iz = 0; iz < nz; iz++)
        for (int iy = 0; iy < ny; iy++)
            for (int ix = 0; ix < nx; ix++) {
                int k = (kdl[iz] * 3 + khl[iy]) * 3 + kwl[ix];
                float val = wc[k] * f0 + wc[27 + k] * f1 + wc[54 + k] * f2;
                size_t sp = (size_t)(odl[iz] + 1) * (PH1 * PW1)
                          + (size_t)(ohl[iy] + 1) * PW1 + (owl[ix] + 1);
                atomicAdd(hc + sp, val);
                if (co == 0) mb[sp] = 1;
            }
}

// ---------------------------------------------------------------------------
// BN+ReLU+mask pass over padded h1, in place. grid=(ceil(PLANE1/1024), B*16)
// ---------------------------------------------------------------------------
__global__ void __launch_bounds__(256)
bn1_pass(float* __restrict__ h, const unsigned char* __restrict__ m,
         const float* __restrict__ Ga, const float* __restrict__ Be,
         const float* __restrict__ Rm, const float* __restrict__ Rv) {
    int c = blockIdx.y & 15;
    int b = blockIdx.y >> 4;
    float inv = Ga[c] * rsqrtf(Rv[c] + EPS);
    float sh  = Be[c] - Rm[c] * inv;
    size_t p = ((size_t)blockIdx.x * 256 + threadIdx.x) * 4;
    if (p >= (size_t)PLANE1) return;
    float4* vp = reinterpret_cast<float4*>(h + (size_t)blockIdx.y * PLANE1 + p);
    float4 v = *vp;
    uchar4 mm = *reinterpret_cast<const uchar4*>(m + (size_t)b * PLANE1 + p);
    v.x = mm.x ? fmaxf(fmaf(v.x, inv, sh), 0.f) : 0.f;
    v.y = mm.y ? fmaxf(fmaf(v.y, inv, sh), 0.f) : 0.f;
    v.z = mm.z ? fmaxf(fmaf(v.z, inv, sh), 0.f) : 0.f;
    v.w = mm.w ? fmaxf(fmaf(v.w, inv, sh), 0.f) : 0.f;
    *vp = v;
}

// ---------------------------------------------------------------------------
// Padded dense conv + BN + ReLU + mask, packed f32x2 FMA.
// Input has halo == conv padding, so id = od*SD+kd etc, NO bounds checks.
// blockDim (32,8). Thread tile: TW outputs along W (32 apart) x TH along H,
// x COG output channels. Output written with halo (OPD,OPH,OPW) for next block.
// ---------------------------------------------------------------------------
template<int CI, int CO, int COG, int TW, int TH,
         int IDP, int IHP, int IWP,
         int OD, int OH, int OW,
         int OPD, int OPH, int OPW,
         int KD, int KH, int KW, int SD, int SH, int SW>
__global__ void __launch_bounds__(256)
conv_pad(const float* __restrict__ in, const unsigned char* __restrict__ mi,
         float* __restrict__ out, unsigned char* __restrict__ mo,
         const float* __restrict__ Wt, const float* __restrict__ Ga,
         const float* __restrict__ Be, const float* __restrict__ Rm,
         const float* __restrict__ Rv) {
    constexpr int NCOG = CO / COG;
    constexpr int NT = TW * TH;      // TW even
    constexpr int NP = NT / 2;
    constexpr int WSTEPS = CI * KD * KH * KW;
    constexpr int ODP = OD + 2 * OPD, OHP = OH + 2 * OPH, OWP = OW + 2 * OPW;
    extern __shared__ u64 sw2[];

    const int tid = threadIdx.y * 32 + threadIdx.x;
    int zi = blockIdx.z;
    const int cg = zi % NCOG; zi /= NCOG;
    const int od = zi % OD;
    const int b  = zi / OD;

    // stage duplicated weights: sw2[(((ci*KD+kd)*KH+kh)*KW+kw)*COG+co] = (w,w)
    for (int i = tid; i < WSTEPS * COG; i += 256) {
        int co = i % COG; int r = i / COG;
        int kw = r % KW; r /= KW;
        int kh = r % KH; r /= KH;
        int kd = r % KD; int ci = r / KD;
        float w = Wt[((((cg * COG + co) * CI + ci) * KD + kd) * KH + kh) * KW + kw];
        sw2[i] = pk2(w, w);
    }
    __syncthreads();

    const int ow0 = blockIdx.x * (32 * TW) + threadIdx.x;      // + 32*tw
    const int oh0 = (blockIdx.y * 8 + threadIdx.y) * TH;       // + th

    // mask = OR of input mask over window, per output
    unsigned any[NT];
#pragma unroll
    for (int t = 0; t < NT; t++) any[t] = 0;
    {
        const unsigned char* mb = mi + (size_t)b * IDP * IHP * IWP;
#pragma unroll
        for (int kd = 0; kd < KD; kd++)
#pragma unroll
            for (int kh = 0; kh < KH; kh++)
#pragma unroll
                for (int th = 0; th < TH; th++) {
                    const unsigned char* mrow =
                        mb + ((size_t)(od * SD + kd) * IHP + (oh0 + th) * SH + kh) * IWP;
#pragma unroll
                    for (int kw = 0; kw < KW; kw++)
#pragma unroll
                        for (int tw = 0; tw < TW; tw++)
                            any[th * TW + tw] |= mrow[(ow0 + 32 * tw) * SW + kw];
                }
    }

    u64 acc[COG][NP];
#pragma unroll
    for (int co = 0; co < COG; co++)
#pragma unroll
        for (int p = 0; p < NP; p++) acc[co][p] = 0ull;

    const float* inb = in + (size_t)b * CI * IDP * IHP * IWP;
#pragma unroll 1
    for (int ci = 0; ci < CI; ci++) {
#pragma unroll
        for (int kd = 0; kd < KD; kd++) {
            const float* pl = inb + ((size_t)ci * IDP + od * SD + kd) * (IHP * IWP);
#pragma unroll
            for (int kh = 0; kh < KH; kh++) {
                const float* row[TH];
#pragma unroll
                for (int th = 0; th < TH; th++)
                    row[th] = pl + ((size_t)(oh0 + th) * SH + kh) * IWP;
#pragma unroll
                for (int kw = 0; kw < KW; kw++) {
                    u64 vp[NP];
#pragma unroll
                    for (int th = 0; th < TH; th++)
#pragma unroll
                        for (int tw = 0; tw < TW; tw += 2) {
                            float a = row[th][(ow0 + 32 * tw) * SW + kw];
                            float c = row[th][(ow0 + 32 * (tw + 1)) * SW + kw];
                            vp[(th * TW + tw) / 2] = pk2(a, c);
                        }
                    const u64* wp = &sw2[(((ci * KD + kd) * KH + kh) * KW + kw) * COG];
#pragma unroll
                    for (int co = 0; co < COG; co++) {
                        u64 w2 = wp[co];
#pragma unroll
                        for (int p = 0; p < NP; p++) fma2(acc[co][p], vp[p], w2);
                    }
                }
            }
        }
    }

    // epilogue: BN + ReLU + mask, write with output halo offsets
#pragma unroll
    for (int co = 0; co < COG; co++) {
        int c = cg * COG + co;
        float inv = Ga[c] * rsqrtf(Rv[c] + EPS);
        float sh  = Be[c] - Rm[c] * inv;
        size_t obc = ((size_t)(b * CO + c) * ODP + od + OPD) * ((size_t)OHP * OWP);
#pragma unroll
        for (int p = 0; p < NP; p++) {
            float a0, a1;
            upk2(acc[co][p], a0, a1);
            int t0 = 2 * p, t1 = 2 * p + 1;
            int th0 = t0 / TW, tw0 = t0 % TW;
            int th1 = t1 / TW, tw1 = t1 % TW;
            float v0 = any[t0] ? fmaxf(fmaf(a0, inv, sh), 0.f) : 0.f;
            float v1 = any[t1] ? fmaxf(fmaf(a1, inv, sh), 0.f) : 0.f;
            out[obc + (size_t)(oh0 + th0 + OPH) * OWP + (ow0 + 32 * tw0 + OPW)] = v0;
            out[obc + (size_t)(oh0 + th1 + OPH) * OWP + (ow0 + 32 * tw1 + OPW)] = v1;
        }
    }
    if (cg == 0) {
        size_t mbc = ((size_t)b * ODP + od + OPD) * ((size_t)OHP * OWP);
#pragma unroll
        for (int t = 0; t < NT; t++) {
            int th = t / TW, tw = t % TW;
            mo[mbc + (size_t)(oh0 + th + OPH) * OWP + (ow0 + 32 * tw + OPW)] = any[t] ? 1 : 0;
        }
    }
}

// ---------------------------------------------------------------------------
extern "C" void kernel_launch(void* const* d_in, const int* in_sizes, int n_in,
                              void* d_out, int out_size) {
    const float* vf    = (const float*)d_in[0];
    const int*   coors = (const int*)d_in[1];
    const float *w1 = (const float*)d_in[3],  *gg1 = (const float*)d_in[4],
                *b1 = (const float*)d_in[5],  *rm1 = (const float*)d_in[6],
                *rv1 = (const float*)d_in[7];
    const float *w2 = (const float*)d_in[8],  *gg2 = (const float*)d_in[9],
                *b2 = (const float*)d_in[10], *rm2 = (const float*)d_in[11],
                *rv2 = (const float*)d_in[12];
    const float *w3 = (const float*)d_in[13], *gg3 = (const float*)d_in[14],
                *b3 = (const float*)d_in[15], *rm3 = (const float*)d_in[16],
                *rv3 = (const float*)d_in[17];
    const float *w4 = (const float*)d_in[18], *gg4 = (const float*)d_in[19],
                *b4 = (const float*)d_in[20], *rm4 = (const float*)d_in[21],
                *rv4 = (const float*)d_in[22];
    float* out = (float*)d_out;
    const int nv = in_sizes[0] / 3;

    float *h1, *h2, *h3;
    unsigned char *m1, *m2, *m3;
    cudaGetSymbolAddress((void**)&h1, g_h1);
    cudaGetSymbolAddress((void**)&m1, g_m1);
    cudaGetSymbolAddress((void**)&h2, g_h2);
    cudaGetSymbolAddress((void**)&m2, g_m2);
    cudaGetSymbolAddress((void**)&h3, g_h3);
    cudaGetSymbolAddress((void**)&m3, g_m3);

    // ---- zero h1 / m1 / h2 / m2 (halos must be clean every call) ----
    {
        long long n4 = (long long)B_ * 16 * PLANE1 / 4;
        zero_f4<<<(unsigned)((n4 + 255) / 256), 256>>>((float4*)h1, (int)n4);
        long long n16 = (B_ * PLANE1 + 8) / 16;
        zero_u4<<<(unsigned)((n16 + 255) / 256), 256>>>((uint4*)m1, (int)n16);
        long long n4b = (long long)B_ * 32 * PLANE2 / 4;
        zero_f4<<<(unsigned)((n4b + 255) / 256), 256>>>((float4*)h2, (int)n4b);
        long long n16b = (B_ * PLANE2 + 8) / 16;
        zero_u4<<<(unsigned)((n16b + 255) / 256), 256>>>((uint4*)m2, (int)n16b);
    }

    // ---- block1 sparse: scatter-conv then BN pass ----
    {
        int nthreads = nv * 16;
        scatter_conv1<<<(nthreads + 255) / 256, 256>>>(vf, coors, h1, m1, w1, nv);
        dim3 grid((unsigned)((PLANE1 / 4 + 255) / 256), B_ * 16);
        bn1_pass<<<grid, 256>>>(h1, m1, gg1, b1, rm1, rv1);
    }

    dim3 blk(32, 8, 1);

    // ---- block2: 16->32, (23,258,258)pad -> (11,128,128) out halo (0,1,1) ----
    {
        auto k = conv_pad<16, 32, 16, 4, 1, 23, 258, 258, 11, 128, 128,
                          0, 1, 1, 3, 3, 3, 2, 2, 2>;
        size_t smem = 27ull * 16 * 16 * 8;   // 55296
        cudaFuncSetAttribute((const void*)k, cudaFuncAttributeMaxDynamicSharedMemorySize,
                             (int)smem);
        dim3 grid(1, 128 / 8, B_ * 11 * 2);
        k<<<grid, blk, smem>>>(h1, m1, h2, m2, w2, gg2, b2, rm2, rv2);
    }
    // ---- block3: 32->64, (11,130,130)pad -> (5,64,64) no out halo ----
    {
        auto k = conv_pad<32, 64, 8, 2, 2, 11, 130, 130, 5, 64, 64,
                          0, 0, 0, 3, 3, 3, 2, 2, 2>;
        size_t smem = 27ull * 32 * 8 * 8;    // 55296
        cudaFuncSetAttribute((const void*)k, cudaFuncAttributeMaxDynamicSharedMemorySize,
                             (int)smem);
        dim3 grid(1, 64 / 16, B_ * 5 * 8);
        k<<<grid, blk, smem>>>(h2, m2, h3, m3, w3, gg3, b3, rm3, rv3);
    }
    // ---- block4: 64->64, k(3,1,1) s(2,1,1), (5,64,64) -> (2,64,64) = d_out ----
    {
        auto k = conv_pad<64, 64, 8, 2, 2, 5, 64, 64, 2, 64, 64,
                          0, 0, 0, 3, 1, 1, 2, 1, 1>;
        size_t smem = 3ull * 64 * 8 * 8;     // 12288
        dim3 grid(1, 64 / 16, B_ * 2 * 8);
        k<<<grid, blk, smem>>>(h3, m3, out, m3, w4, gg4, b4, rm4, rv4);
    }
}